// round 1
// baseline (speedup 1.0000x reference)
#include <cuda_runtime.h>
#include <cstdint>

// Problem constants (fixed by the reference: B=8, N=16384, RATIO=0.5, C=128)
#define BB 8
#define NN 16384
#define NPOINT 8192
#define CC 128
#define T 1024
#define PPT (NN / T)   // 16 points per thread

// Scratch: selected indices per batch (device global — no allocation allowed)
__device__ int g_idx[BB * NPOINT];

// ---------------------------------------------------------------------------
// FPS kernel: one CTA per batch. xyz SoA mirrored in SMEM (for centroid
// lookup + z loads); x,y,dist register-resident per thread.
// Argmax uses packed u64 key = (dist_bits<<32)|(N-1-idx) so max-reduce gives
// (max dist, first index) exactly like jnp.argmax tie-breaking.
// ---------------------------------------------------------------------------
extern "C" __global__ void __launch_bounds__(T, 1)
fps_kernel(const float* __restrict__ xyz) {
    const int b = blockIdx.x;
    const int t = threadIdx.x;
    const float* __restrict__ p = xyz + (size_t)b * NN * 3;

    extern __shared__ float smem[];
    float* sx = smem;            // [NN]
    float* sy = smem + NN;       // [NN]
    float* sz = smem + 2 * NN;   // [NN]
    unsigned long long* rk = (unsigned long long*)(smem + 3 * NN); // [32]
    unsigned long long* bk = rk + 32;                              // [1]

    float xs[PPT], ys[PPT], dist[PPT];

    // Load xyz (AoS global) -> registers + SMEM SoA
#pragma unroll
    for (int k = 0; k < PPT; k++) {
        int i = t + k * T;
        float x = p[i * 3 + 0];
        float y = p[i * 3 + 1];
        float z = p[i * 3 + 2];
        xs[k] = x; ys[k] = y;
        sx[i] = x; sy[i] = y; sz[i] = z;
        dist[k] = 1e10f;
    }
    __syncthreads();

    int f = 0;  // init_far = 0, matches reference
    int* __restrict__ idxo = g_idx + b * NPOINT;

    for (int j = 0; j < NPOINT; j++) {
        if (t == 0) idxo[j] = f;   // scan emits farthest BEFORE update (ref semantics)

        float cx = sx[f];
        float cy = sy[f];
        float cz = sz[f];

        float best = -1.0f;
        int bi = t;
#pragma unroll
        for (int k = 0; k < PPT; k++) {
            float dx = xs[k] - cx;
            float dy = ys[k] - cy;
            float dz = sz[t + k * T] - cz;
            float d = dx * dx + dy * dy + dz * dz;
            float nd = fminf(dist[k], d);
            dist[k] = nd;
            if (nd > best) { best = nd; bi = t + k * T; }  // strict >: keeps lowest k
        }

        // packed key: higher dist wins; equal dist -> larger (N-1-bi) -> smaller bi
        unsigned long long key =
            ((unsigned long long)__float_as_uint(best) << 32) |
            (unsigned long long)(unsigned)(NN - 1 - bi);

#pragma unroll
        for (int off = 16; off > 0; off >>= 1) {
            unsigned long long o = __shfl_down_sync(0xFFFFFFFFu, key, off);
            key = (o > key) ? o : key;
        }
        if ((t & 31) == 0) rk[t >> 5] = key;
        __syncthreads();

        if (t < 32) {
            unsigned long long k2 = rk[t];
#pragma unroll
            for (int off = 16; off > 0; off >>= 1) {
                unsigned long long o = __shfl_down_sync(0xFFFFFFFFu, k2, off);
                k2 = (o > k2) ? o : k2;
            }
            if (t == 0) *bk = k2;
        }
        __syncthreads();

        f = NN - 1 - (int)((unsigned)(*bk) & 0xFFFFu);
    }
}

// ---------------------------------------------------------------------------
// Gather feats: out[b][c][m] = feats[b][c][ idx[b][m] ]
// Linear index l = (b*C + c)*NPOINT + m -> consecutive threads share (b,c),
// writes coalesced, reads gather within a 64KB row (L2-friendly).
// ---------------------------------------------------------------------------
extern "C" __global__ void gather_feats_kernel(const float* __restrict__ feats,
                                               float* __restrict__ out) {
    long long l = (long long)blockIdx.x * blockDim.x + threadIdx.x;
    const long long total = (long long)BB * CC * NPOINT;
    if (l >= total) return;
    int m = (int)(l % NPOINT);
    long long bc = l / NPOINT;          // b*C + c
    int b = (int)(bc / CC);
    int i = g_idx[b * NPOINT + m];
    out[l] = feats[bc * NN + i];
}

// ---------------------------------------------------------------------------
// Gather xyz: out[b][m][d] = xyz[b][idx[b][m]][d]
// ---------------------------------------------------------------------------
extern "C" __global__ void gather_xyz_kernel(const float* __restrict__ xyz,
                                             float* __restrict__ out) {
    int l = blockIdx.x * blockDim.x + threadIdx.x;   // over B*NPOINT
    if (l >= BB * NPOINT) return;
    int b = l / NPOINT;
    int i = g_idx[l];
    const float* src = xyz + ((size_t)b * NN + i) * 3;
    float* dst = out + (size_t)l * 3;
    dst[0] = src[0];
    dst[1] = src[1];
    dst[2] = src[2];
}

// ---------------------------------------------------------------------------
extern "C" void kernel_launch(void* const* d_in, const int* in_sizes, int n_in,
                              void* d_out, int out_size) {
    // Identify inputs by element count (robust to ordering):
    // feats = 8*128*16384 = 16777216, xyz = 8*16384*3 = 393216
    const float* feats = (const float*)d_in[0];
    const float* xyz   = (const float*)d_in[1];
    if (in_sizes[0] == BB * NN * 3) {
        xyz   = (const float*)d_in[0];
        feats = (const float*)d_in[1];
    }

    float* out = (float*)d_out;
    float* out_feats = out;                                   // B*C*NPOINT
    float* out_xyz   = out + (size_t)BB * CC * NPOINT;        // B*NPOINT*3

    size_t smem = 3 * NN * sizeof(float) + 33 * sizeof(unsigned long long);
    static bool attr_set = false;
    // cudaFuncSetAttribute is not a stream op; safe under graph capture.
    cudaFuncSetAttribute(fps_kernel,
                         cudaFuncAttributeMaxDynamicSharedMemorySize,
                         (int)smem);
    (void)attr_set;

    fps_kernel<<<BB, T, smem>>>(xyz);

    const long long feat_total = (long long)BB * CC * NPOINT;
    int gb = (int)((feat_total + 255) / 256);
    gather_feats_kernel<<<gb, 256>>>(feats, out_feats);

    int xb = (BB * NPOINT + 255) / 256;
    gather_xyz_kernel<<<xb, 256>>>(xyz, out_xyz);
}

// round 3
// speedup vs baseline: 1.8356x; 1.8356x over previous
#include <cuda_runtime.h>
#include <cstdint>

// Problem constants (fixed by the reference: B=8, N=16384, RATIO=0.5, C=128)
#define BB 8
#define NN 16384
#define NPOINT 8192
#define CC 128
#define T 1024
#define CSIZE 8              // CTAs per batch (cluster size)
#define NC (NN / CSIZE)      // 2048 points per CTA
#define NWARP (T / 32)       // 32 warps

typedef unsigned long long u64;
typedef unsigned int u32;

// Scratch: selected indices per batch (device global — no allocation allowed)
__device__ int g_idx[BB * NPOINT];

// ---------------------------------------------------------------------------
// helpers
// ---------------------------------------------------------------------------
__device__ __forceinline__ u32 smem_u32(const void* p) {
    return (u32)__cvta_generic_to_shared(p);
}
__device__ __forceinline__ void vst64(u32 a, u64 v) {
    asm volatile("st.volatile.shared.b64 [%0], %1;" :: "r"(a), "l"(v) : "memory");
}
__device__ __forceinline__ u64 vld64(u32 a) {
    u64 v;
    asm volatile("ld.volatile.shared.b64 %0, [%1];" : "=l"(v) : "r"(a) : "memory");
    return v;
}
__device__ __forceinline__ void vst32(u32 a, u32 v) {
    asm volatile("st.volatile.shared.b32 [%0], %1;" :: "r"(a), "r"(v) : "memory");
}
__device__ __forceinline__ u32 vld32(u32 a) {
    u32 v;
    asm volatile("ld.volatile.shared.b32 %0, [%1];" : "=r"(v) : "r"(a) : "memory");
    return v;
}
// remote store of a tagged 64-bit key into peer CTA's smem (cluster DSMEM)
__device__ __forceinline__ void st_remote64(u32 laddr, u32 rank, u64 v) {
    u32 ra;
    asm volatile("mapa.shared::cluster.u32 %0, %1, %2;" : "=r"(ra) : "r"(laddr), "r"(rank));
    asm volatile("st.relaxed.cluster.shared::cluster.b64 [%0], %1;" :: "r"(ra), "l"(v) : "memory");
}

// ---------------------------------------------------------------------------
// FPS: 8-CTA cluster per batch. Each CTA owns 2048 points (2/thread, all in
// registers). Distance arithmetic is the VERBATIM scalar expression from the
// round-1 kernel (rel_err == 0.0) so the compiler picks the same contraction;
// the round-2 hand-packed f32x2 fma order flipped a handful of near-tie
// selections.
//
// Argmax reduction per iteration:
//   warp:    2x REDUX (dist bits, then first-index among maxima)
//   CTA:     warp leaders post tagged u64 keys to smem; warp0 spins + REDUX
//   cluster: warp0 lane0 broadcasts CTA key to all ranks via DSMEM; warp0
//            spins on 8 tagged slots + REDUX; posts tagged f to fSlot
//   others:  spin on fSlot
// Keys: (dist_bits<<32) | (tag<<16) | (NN-1-idx)  — max gives (max dist,
// first index), exactly matching jnp.argmax tie-breaking. Tags make the spin
// protocol self-synchronizing; double buffering (j&1) prevents overwrite of
// a slot a laggard warp is still polling.
// ---------------------------------------------------------------------------
extern "C" __global__ void __launch_bounds__(T, 1) __cluster_dims__(CSIZE, 1, 1)
fps_kernel(const float* __restrict__ xyz)
{
    const int blk  = blockIdx.x;
    const int b    = blk / CSIZE;
    const u32 rank = (u32)(blk % CSIZE);
    const int tid  = threadIdx.x;
    const int wid  = tid >> 5;
    const int lane = tid & 31;

    extern __shared__ float smem[];
    float* sx = smem;                               // [NN]
    float* sy = smem + NN;                          // [NN]
    float* sz = smem + 2 * NN;                      // [NN]
    u64* warpSlots  = (u64*)(smem + 3 * NN);        // [2][NWARP]
    u64* crossSlots = warpSlots + 2 * NWARP;        // [2][CSIZE]
    u32* fSlot      = (u32*)(crossSlots + 2 * CSIZE); // [2]

    const float* __restrict__ p = xyz + (size_t)b * NN * 3;

    // Full xyz table in smem (centroid lookup must cover all 16384 points)
    for (int i = tid; i < NN; i += T) {
        sx[i] = p[3 * i + 0];
        sy[i] = p[3 * i + 1];
        sz[i] = p[3 * i + 2];
    }
    if (tid < 2 * NWARP) warpSlots[tid] = 0ull;
    if (tid < 2 * CSIZE) crossSlots[tid] = 0ull;
    if (tid < 2)         fSlot[tid] = 0u;
    __syncthreads();
    // all CTAs' slots must be zeroed before any peer's first DSMEM store
    asm volatile("barrier.cluster.arrive.aligned;" ::: "memory");
    asm volatile("barrier.cluster.wait.aligned;"   ::: "memory");

    // Own 2 points, register-resident (i0 < i1)
    const int i0 = (int)rank * NC + tid;
    const int i1 = i0 + T;
    const float X0 = sx[i0], Y0 = sy[i0], Z0 = sz[i0];
    const float X1 = sx[i1], Y1 = sy[i1], Z1 = sz[i1];
    float D0 = 1e10f, D1 = 1e10f;

    const u32 wsBase = smem_u32(warpSlots);
    const u32 csBase = smem_u32(crossSlots);
    const u32 fsBase = smem_u32(fSlot);

    int f = 0;   // init_far = 0 (reference)
    int* __restrict__ idxo = g_idx + b * NPOINT;

    for (int j = 0; j < NPOINT; j++) {
        const u32 tag = (u32)(j + 1);   // 1..8192, fits 14 bits
        const int buf = j & 1;

        if (rank == 0 && tid == 0) idxo[j] = f;  // scan emits farthest BEFORE update

        // distance update — IDENTICAL source expression to the round-1 kernel
        const float cx = sx[f], cy = sy[f], cz = sz[f];

        float best = -1.0f;
        int bi = i0;
        {
            float dx = X0 - cx;
            float dy = Y0 - cy;
            float dz = Z0 - cz;
            float d = dx * dx + dy * dy + dz * dz;
            float nd = fminf(D0, d);
            D0 = nd;
            if (nd > best) { best = nd; bi = i0; }
        }
        {
            float dx = X1 - cx;
            float dy = Y1 - cy;
            float dz = Z1 - cz;
            float d = dx * dx + dy * dy + dz * dz;
            float nd = fminf(D1, d);
            D1 = nd;
            if (nd > best) { best = nd; bi = i1; }   // strict >: ties keep i0
        }

        // warp-level: max dist bits, then max of (NN-1-idx) among maxima
        const u32 ub  = __float_as_uint(best);          // dist >= 0: bit order == float order
        const u32 wm  = __reduce_max_sync(0xFFFFFFFFu, ub);
        const u32 cnd = (ub == wm) ? (u32)(NN - 1 - bi) : 0u;
        const u32 wi  = __reduce_max_sync(0xFFFFFFFFu, cnd);

        if (lane == 0) {
            const u64 wkey = ((u64)wm << 32) | ((u64)tag << 16) | (u64)wi;
            vst64(wsBase + (u32)((buf * NWARP + wid) * 8), wkey);
        }

        if (wid == 0) {
            // ---- CTA reduce: 32 slots <-> 32 lanes ----
            const u32 myslot = wsBase + (u32)((buf * NWARP + lane) * 8);
            u64 k;
            do { k = vld64(myslot); }
            while (__any_sync(0xFFFFFFFFu, ((u32)k >> 16) != tag));
            const u32 hi = (u32)(k >> 32);
            const u32 lo = (u32)k;
            const u32 m1 = __reduce_max_sync(0xFFFFFFFFu, hi);
            const u32 c1 = (hi == m1) ? lo : 0u;
            const u32 m2 = __reduce_max_sync(0xFFFFFFFFu, c1);
            const u64 ckey = ((u64)m1 << 32) | (u64)m2;

            // ---- cluster broadcast: write my CTA key into slot[rank] of all ranks ----
            if (lane == 0) {
                const u32 slotOff = (u32)((buf * CSIZE + (int)rank) * 8);
                #pragma unroll
                for (u32 r = 0; r < CSIZE; r++)
                    st_remote64(csBase + slotOff, r, ckey);
            }
            // ---- cluster reduce: lanes 0..7 poll the 8 slots ----
            const u32 cslot = csBase + (u32)((buf * CSIZE + (lane & (CSIZE - 1))) * 8);
            u64 ck; bool ok;
            do {
                ck = vld64(cslot);
                ok = (lane >= CSIZE) || (((u32)ck >> 16) == tag);
            } while (!__all_sync(0xFFFFFFFFu, ok));
            const u32 chi = (lane < CSIZE) ? (u32)(ck >> 32) : 0u;
            const u32 clo = (u32)ck;
            const u32 M1 = __reduce_max_sync(0xFFFFFFFFu, chi);
            const u32 C1 = (lane < CSIZE && chi == M1) ? clo : 0u;
            const u32 M2 = __reduce_max_sync(0xFFFFFFFFu, C1);
            f = NN - 1 - (int)(M2 & 0x3FFFu);
            if (lane == 0) vst32(fsBase + (u32)(buf * 4), (tag << 16) | (u32)f);
        } else {
            const u32 fa = fsBase + (u32)(buf * 4);
            u32 v;
            do { v = vld32(fa); } while ((v >> 16) != tag);
            f = (int)(v & 0xFFFFu);
        }
    }
}

// ---------------------------------------------------------------------------
// Gather feats: out[b][c][m] = feats[b][c][ idx[b][m] ]
// ---------------------------------------------------------------------------
extern "C" __global__ void gather_feats_kernel(const float* __restrict__ feats,
                                               float* __restrict__ out) {
    long long l = (long long)blockIdx.x * blockDim.x + threadIdx.x;
    const long long total = (long long)BB * CC * NPOINT;
    if (l >= total) return;
    int m = (int)(l % NPOINT);
    long long bc = l / NPOINT;          // b*C + c
    int b = (int)(bc / CC);
    int i = g_idx[b * NPOINT + m];
    out[l] = feats[bc * NN + i];
}

// ---------------------------------------------------------------------------
// Gather xyz: out[b][m][d] = xyz[b][idx[b][m]][d]
// ---------------------------------------------------------------------------
extern "C" __global__ void gather_xyz_kernel(const float* __restrict__ xyz,
                                             float* __restrict__ out) {
    int l = blockIdx.x * blockDim.x + threadIdx.x;   // over B*NPOINT
    if (l >= BB * NPOINT) return;
    int b = l / NPOINT;
    int i = g_idx[l];
    const float* src = xyz + ((size_t)b * NN + i) * 3;
    float* dst = out + (size_t)l * 3;
    dst[0] = src[0];
    dst[1] = src[1];
    dst[2] = src[2];
}

// ---------------------------------------------------------------------------
extern "C" void kernel_launch(void* const* d_in, const int* in_sizes, int n_in,
                              void* d_out, int out_size) {
    // Identify inputs by element count (robust to ordering):
    // feats = 8*128*16384 = 16777216, xyz = 8*16384*3 = 393216
    const float* feats = (const float*)d_in[0];
    const float* xyz   = (const float*)d_in[1];
    if (in_sizes[0] == BB * NN * 3) {
        xyz   = (const float*)d_in[0];
        feats = (const float*)d_in[1];
    }

    float* out = (float*)d_out;
    float* out_feats = out;                                   // B*C*NPOINT
    float* out_xyz   = out + (size_t)BB * CC * NPOINT;        // B*NPOINT*3

    const size_t smem = (size_t)3 * NN * sizeof(float)
                      + 2 * NWARP * sizeof(u64)
                      + 2 * CSIZE * sizeof(u64)
                      + 2 * sizeof(u32);
    cudaFuncSetAttribute(fps_kernel,
                         cudaFuncAttributeMaxDynamicSharedMemorySize,
                         (int)smem);

    fps_kernel<<<BB * CSIZE, T, smem>>>(xyz);

    const long long feat_total = (long long)BB * CC * NPOINT;
    int gb = (int)((feat_total + 255) / 256);
    gather_feats_kernel<<<gb, 256>>>(feats, out_feats);

    int xb = (BB * NPOINT + 255) / 256;
    gather_xyz_kernel<<<xb, 256>>>(xyz, out_xyz);
}

// round 4
// speedup vs baseline: 2.7133x; 1.4782x over previous
#include <cuda_runtime.h>
#include <cstdint>

// Problem constants (fixed by the reference: B=8, N=16384, RATIO=0.5, C=128)
#define BB 8
#define NN 16384
#define NPOINT 8192
#define CC 128
#define T 256                // threads per CTA (8 warps)
#define CSIZE 8              // CTAs per batch (cluster size)
#define NC (NN / CSIZE)      // 2048 points per CTA
#define NWARP (T / 32)       // 8 warps
#define PPT (NC / T)         // 8 points per thread

typedef unsigned long long u64;
typedef unsigned int u32;

// Scratch: selected indices per batch (device global — no allocation allowed)
__device__ int g_idx[BB * NPOINT];

// ---------------------------------------------------------------------------
// helpers
// ---------------------------------------------------------------------------
__device__ __forceinline__ u32 smem_u32(const void* p) {
    return (u32)__cvta_generic_to_shared(p);
}
__device__ __forceinline__ void vst64(u32 a, u64 v) {
    asm volatile("st.volatile.shared.b64 [%0], %1;" :: "r"(a), "l"(v) : "memory");
}
__device__ __forceinline__ u64 vld64(u32 a) {
    u64 v;
    asm volatile("ld.volatile.shared.b64 %0, [%1];" : "=l"(v) : "r"(a) : "memory");
    return v;
}
// remote store of a tagged 64-bit key into peer CTA's smem (cluster DSMEM)
__device__ __forceinline__ void st_remote64(u32 laddr, u32 rank, u64 v) {
    u32 ra;
    asm volatile("mapa.shared::cluster.u32 %0, %1, %2;" : "=r"(ra) : "r"(laddr), "r"(rank));
    asm volatile("st.relaxed.cluster.shared::cluster.b64 [%0], %1;" :: "r"(ra), "l"(v) : "memory");
}

// ---------------------------------------------------------------------------
// FPS: 8-CTA cluster per batch, 256 threads/CTA, 8 points/thread (registers).
// Per-point distance arithmetic is the VERBATIM scalar expression from the
// rel_err==0.0 kernels (rounds 1/3) — do not touch.
//
// Per-iteration reduction:
//   thread:  3-level pairwise argmax tree over 8 points (prefer-left = lower
//            index on ties, exact jnp.argmax semantics)
//   warp:    2x REDUX (dist bits, then max(NN-1-idx) among maxima)
//   CTA:     8 warp leaders post tagged u64 keys; warp0 polls + REDUX
//   cluster: warp0 lane0 DSMEM-broadcasts CTA key to slot[rank] of all ranks;
//            then EVERY warp polls the 8 cross slots and redundantly computes
//            the cluster argmax (no extra broadcast hop).
// Keys: (dist_bits<<32) | (tag<<16) | (NN-1-idx). Tags self-synchronize the
// spin protocol; double buffering (j&1) prevents overwrite races: rank r can
// only reach iter j+2's store after its j+1 CTA key existed, which requires
// every warp of every CTA to have consumed iter j's slots.
// ---------------------------------------------------------------------------
extern "C" __global__ void __launch_bounds__(T, 1) __cluster_dims__(CSIZE, 1, 1)
fps_kernel(const float* __restrict__ xyz)
{
    const int blk  = blockIdx.x;
    const int b    = blk / CSIZE;
    const u32 rank = (u32)(blk % CSIZE);
    const int tid  = threadIdx.x;
    const int wid  = tid >> 5;
    const int lane = tid & 31;

    extern __shared__ float smem[];
    float* sx = smem;                               // [NN]
    float* sy = smem + NN;                          // [NN]
    float* sz = smem + 2 * NN;                      // [NN]
    u64* warpSlots  = (u64*)(smem + 3 * NN);        // [2][NWARP]
    u64* crossSlots = warpSlots + 2 * NWARP;        // [2][CSIZE]

    const float* __restrict__ p = xyz + (size_t)b * NN * 3;

    // Full xyz table in smem (centroid lookup must cover all 16384 points)
    for (int i = tid; i < NN; i += T) {
        sx[i] = p[3 * i + 0];
        sy[i] = p[3 * i + 1];
        sz[i] = p[3 * i + 2];
    }
    if (tid < 2 * NWARP) warpSlots[tid] = 0ull;
    if (tid < 2 * CSIZE) crossSlots[tid] = 0ull;
    __syncthreads();
    // all CTAs' slots must be zeroed before any peer's first DSMEM store
    asm volatile("barrier.cluster.arrive.aligned;" ::: "memory");
    asm volatile("barrier.cluster.wait.aligned;"   ::: "memory");

    // Own 8 points, register-resident: i_k = base + k*T (k ascending => index ascending)
    const int base = (int)rank * NC + tid;
    float X[PPT], Y[PPT], Z[PPT], D[PPT];
#pragma unroll
    for (int k = 0; k < PPT; k++) {
        const int i = base + k * T;
        X[k] = sx[i]; Y[k] = sy[i]; Z[k] = sz[i];
        D[k] = 1e10f;
    }

    const u32 wsBase = smem_u32(warpSlots);
    const u32 csBase = smem_u32(crossSlots);

    int f = 0;   // init_far = 0 (reference)
    int* __restrict__ idxo = g_idx + b * NPOINT;

    for (int j = 0; j < NPOINT; j++) {
        const u32 tag = (u32)(j + 1);   // 1..8192
        const int buf = j & 1;

        if (rank == 0 && tid == 0) idxo[j] = f;  // scan emits farthest BEFORE update

        // distance update — IDENTICAL source expression to rounds 1/3
        const float cx = sx[f], cy = sy[f], cz = sz[f];
        float nd[PPT];
#pragma unroll
        for (int k = 0; k < PPT; k++) {
            float dx = X[k] - cx;
            float dy = Y[k] - cy;
            float dz = Z[k] - cz;
            float d = dx * dx + dy * dy + dz * dz;
            float v = fminf(D[k], d);
            D[k] = v;
            nd[k] = v;
        }

        // thread-level argmax tree over 8 values; prefer-left keeps lowest k
        // (k ascending == global index ascending), i.e. first-index tie-break.
        float bd[PPT]; int bk[PPT];
#pragma unroll
        for (int k = 0; k < PPT; k++) { bd[k] = nd[k]; bk[k] = k; }
#pragma unroll
        for (int s = PPT / 2; s > 0; s >>= 1) {
#pragma unroll
            for (int k = 0; k < PPT; k++) {
                if (k < s) {
                    // right wins only if STRICTLY greater
                    if (bd[k + s] > bd[k]) { bd[k] = bd[k + s]; bk[k] = bk[k + s]; }
                }
            }
        }
        const float best = bd[0];
        const int   bi   = base + bk[0] * T;

        // warp-level: max dist bits, then max of (NN-1-idx) among maxima
        const u32 ub  = __float_as_uint(best);          // dist >= 0: bit order == float order
        const u32 wm  = __reduce_max_sync(0xFFFFFFFFu, ub);
        const u32 cnd = (ub == wm) ? (u32)(NN - 1 - bi) : 0u;
        const u32 wi  = __reduce_max_sync(0xFFFFFFFFu, cnd);

        if (lane == 0) {
            const u64 wkey = ((u64)wm << 32) | ((u64)tag << 16) | (u64)wi;
            vst64(wsBase + (u32)((buf * NWARP + wid) * 8), wkey);
        }

        if (wid == 0) {
            // ---- CTA reduce: 8 slots, lanes read slot (lane&7) ----
            const u32 myslot = wsBase + (u32)((buf * NWARP + (lane & (NWARP - 1))) * 8);
            u64 k;
            do { k = vld64(myslot); }
            while (__any_sync(0xFFFFFFFFu, ((u32)k >> 16) != tag));
            const u32 hi = (u32)(k >> 32);
            const u32 lo = (u32)k;
            const u32 m1 = __reduce_max_sync(0xFFFFFFFFu, hi);
            const u32 c1 = (hi == m1) ? lo : 0u;
            const u32 m2 = __reduce_max_sync(0xFFFFFFFFu, c1);
            const u64 ckey = ((u64)m1 << 32) | (u64)m2;

            // ---- cluster broadcast: write my CTA key into slot[rank] of all ranks ----
            if (lane == 0) {
                const u32 slotOff = (u32)((buf * CSIZE + (int)rank) * 8);
                #pragma unroll
                for (u32 r = 0; r < CSIZE; r++)
                    st_remote64(csBase + slotOff, r, ckey);
            }
        }

        // ---- cluster reduce: EVERY warp polls the 8 cross slots + reduces ----
        {
            const u32 cslot = csBase + (u32)((buf * CSIZE + (lane & (CSIZE - 1))) * 8);
            u64 ck;
            do { ck = vld64(cslot); }
            while (__any_sync(0xFFFFFFFFu, ((u32)ck >> 16) != tag));
            const u32 chi = (u32)(ck >> 32);
            const u32 clo = (u32)ck;
            const u32 M1 = __reduce_max_sync(0xFFFFFFFFu, chi);
            const u32 C1 = (chi == M1) ? clo : 0u;
            const u32 M2 = __reduce_max_sync(0xFFFFFFFFu, C1);
            f = NN - 1 - (int)(M2 & 0x3FFFu);
        }
    }
}

// ---------------------------------------------------------------------------
// Gather feats: out[b][c][m] = feats[b][c][ idx[b][m] ]
// ---------------------------------------------------------------------------
extern "C" __global__ void gather_feats_kernel(const float* __restrict__ feats,
                                               float* __restrict__ out) {
    long long l = (long long)blockIdx.x * blockDim.x + threadIdx.x;
    const long long total = (long long)BB * CC * NPOINT;
    if (l >= total) return;
    int m = (int)(l % NPOINT);
    long long bc = l / NPOINT;          // b*C + c
    int b = (int)(bc / CC);
    int i = g_idx[b * NPOINT + m];
    out[l] = feats[bc * NN + i];
}

// ---------------------------------------------------------------------------
// Gather xyz: out[b][m][d] = xyz[b][idx[b][m]][d]
// ---------------------------------------------------------------------------
extern "C" __global__ void gather_xyz_kernel(const float* __restrict__ xyz,
                                             float* __restrict__ out) {
    int l = blockIdx.x * blockDim.x + threadIdx.x;   // over B*NPOINT
    if (l >= BB * NPOINT) return;
    int b = l / NPOINT;
    int i = g_idx[l];
    const float* src = xyz + ((size_t)b * NN + i) * 3;
    float* dst = out + (size_t)l * 3;
    dst[0] = src[0];
    dst[1] = src[1];
    dst[2] = src[2];
}

// ---------------------------------------------------------------------------
extern "C" void kernel_launch(void* const* d_in, const int* in_sizes, int n_in,
                              void* d_out, int out_size) {
    // Identify inputs by element count (robust to ordering):
    // feats = 8*128*16384 = 16777216, xyz = 8*16384*3 = 393216
    const float* feats = (const float*)d_in[0];
    const float* xyz   = (const float*)d_in[1];
    if (in_sizes[0] == BB * NN * 3) {
        xyz   = (const float*)d_in[0];
        feats = (const float*)d_in[1];
    }

    float* out = (float*)d_out;
    float* out_feats = out;                                   // B*C*NPOINT
    float* out_xyz   = out + (size_t)BB * CC * NPOINT;        // B*NPOINT*3

    const size_t smem = (size_t)3 * NN * sizeof(float)
                      + 2 * NWARP * sizeof(u64)
                      + 2 * CSIZE * sizeof(u64);
    cudaFuncSetAttribute(fps_kernel,
                         cudaFuncAttributeMaxDynamicSharedMemorySize,
                         (int)smem);

    fps_kernel<<<BB * CSIZE, T, smem>>>(xyz);

    const long long feat_total = (long long)BB * CC * NPOINT;
    int gb = (int)((feat_total + 255) / 256);
    gather_feats_kernel<<<gb, 256>>>(feats, out_feats);

    int xb = (BB * NPOINT + 255) / 256;
    gather_xyz_kernel<<<xb, 256>>>(xyz, out_xyz);
}

// round 5
// speedup vs baseline: 3.3773x; 1.2447x over previous
#include <cuda_runtime.h>
#include <cstdint>

// Problem constants (fixed by the reference: B=8, N=16384, RATIO=0.5, C=128)
#define BB 8
#define NN 16384
#define NPOINT 8192
#define CC 128
#define T 256                // threads per CTA (8 warps)
#define CSIZE 8              // CTAs per batch (cluster size)
#define NC (NN / CSIZE)      // 2048 points per CTA
#define NWARP (T / 32)       // 8 warps
#define PPT (NC / T)         // 8 points per thread
#define NSLOT (CSIZE * NWARP)  // 64 cross slots per buffer

typedef unsigned long long u64;
typedef unsigned int u32;

// Scratch: selected indices per batch (device global — no allocation allowed)
__device__ int g_idx[BB * NPOINT];

// ---------------------------------------------------------------------------
// helpers
// ---------------------------------------------------------------------------
__device__ __forceinline__ u32 smem_u32(const void* p) {
    return (u32)__cvta_generic_to_shared(p);
}
__device__ __forceinline__ u64 vld64(u32 a) {
    u64 v;
    asm volatile("ld.volatile.shared.b64 %0, [%1];" : "=l"(v) : "r"(a) : "memory");
    return v;
}
__device__ __forceinline__ u32 mapa_rank(u32 laddr, u32 rank) {
    u32 ra;
    asm volatile("mapa.shared::cluster.u32 %0, %1, %2;" : "=r"(ra) : "r"(laddr), "r"(rank));
    return ra;
}
__device__ __forceinline__ void st_cluster64(u32 raddr, u64 v) {
    asm volatile("st.relaxed.cluster.shared::cluster.b64 [%0], %1;" :: "r"(raddr), "l"(v) : "memory");
}

// ---------------------------------------------------------------------------
// FPS: 8-CTA cluster per batch, 256 threads/CTA, 8 points/thread (registers).
// Per-point distance arithmetic is the VERBATIM scalar expression from the
// rel_err==0.0 kernels (rounds 1/3/4) — do not touch.
//
// ONE-STAGE reduction per iteration (round-5 change: the CTA-level
// intermediate stage is gone):
//   thread:  pairwise argmax tree over 8 points (prefer-left = lower index
//            on ties, exact jnp.argmax semantics)
//   warp:    2x REDUX -> warp key
//   all-to-all: each warp leader DSMEM-stores its warp key into slot
//            [rank*NWARP+wid] of ALL 8 ranks (peer addresses precomputed
//            via mapa outside the loop)
//   every warp: polls all 64 tagged slots (2 per lane), local u64 max,
//            then 2x REDUX -> f. No further broadcast needed.
// Keys: (dist_bits<<32) | (tag<<16) | (NN-1-idx); tags (14 bits) make the
// spin protocol self-synchronizing; within one iteration all tags are equal
// so u64 max == (max dist, then first index) — jnp.argmax tie-breaking.
// Double buffering (j&1) prevents overwrite races: warp w writes buffer
// (j+2)&1 only after passing poll j+1, which required every warp to have
// posted j+1, which required every warp to have finished reading buffer j&1.
// ---------------------------------------------------------------------------
extern "C" __global__ void __launch_bounds__(T, 1) __cluster_dims__(CSIZE, 1, 1)
fps_kernel(const float* __restrict__ xyz)
{
    const int blk  = blockIdx.x;
    const int b    = blk / CSIZE;
    const u32 rank = (u32)(blk % CSIZE);
    const int tid  = threadIdx.x;
    const int wid  = tid >> 5;
    const int lane = tid & 31;

    extern __shared__ float smem[];
    float* sx = smem;                               // [NN]
    float* sy = smem + NN;                          // [NN]
    float* sz = smem + 2 * NN;                      // [NN]
    u64* crossSlots = (u64*)(smem + 3 * NN);        // [2][NSLOT]

    const float* __restrict__ p = xyz + (size_t)b * NN * 3;

    // Full xyz table in smem (centroid lookup must cover all 16384 points)
    for (int i = tid; i < NN; i += T) {
        sx[i] = p[3 * i + 0];
        sy[i] = p[3 * i + 1];
        sz[i] = p[3 * i + 2];
    }
    if (tid < 2 * NSLOT) crossSlots[tid] = 0ull;
    __syncthreads();
    // all CTAs' slots must be zeroed before any peer's first DSMEM store
    asm volatile("barrier.cluster.arrive.aligned;" ::: "memory");
    asm volatile("barrier.cluster.wait.aligned;"   ::: "memory");

    // Own 8 points, register-resident: i_k = base + k*T (k ascending => index ascending)
    const int base = (int)rank * NC + tid;
    float X[PPT], Y[PPT], Z[PPT], D[PPT];
#pragma unroll
    for (int k = 0; k < PPT; k++) {
        const int i = base + k * T;
        X[k] = sx[i]; Y[k] = sy[i]; Z[k] = sz[i];
        D[k] = 1e10f;
    }

    const u32 csBase = smem_u32(crossSlots);

    // Precompute peer addresses of MY slot in every rank's crossSlots
    // (byte offset of slot [rank*NWARP+wid] added per-iteration via buf).
    u32 peer[CSIZE];
#pragma unroll
    for (int r = 0; r < CSIZE; r++)
        peer[r] = mapa_rank(csBase, (u32)r)
                + (u32)(((int)rank * NWARP + wid) * 8);

    // The two slots this lane polls (64 slots, 2 per lane)
    const u32 poll0 = csBase + (u32)(lane * 8);
    const u32 poll1 = csBase + (u32)((lane + 32) * 8);

    int f = 0;   // init_far = 0 (reference)
    int* __restrict__ idxo = g_idx + b * NPOINT;

    for (int j = 0; j < NPOINT; j++) {
        const u32 tag = (u32)(j + 1);   // 1..8192 (14 bits)
        const u32 bufOff = (u32)((j & 1) * (NSLOT * 8));

        if (rank == 0 && tid == 0) idxo[j] = f;  // scan emits farthest BEFORE update

        // distance update — IDENTICAL source expression to rounds 1/3/4
        const float cx = sx[f], cy = sy[f], cz = sz[f];
        float nd[PPT];
#pragma unroll
        for (int k = 0; k < PPT; k++) {
            float dx = X[k] - cx;
            float dy = Y[k] - cy;
            float dz = Z[k] - cz;
            float d = dx * dx + dy * dy + dz * dz;
            float v = fminf(D[k], d);
            D[k] = v;
            nd[k] = v;
        }

        // thread-level argmax tree over 8 values; prefer-left keeps lowest k
        // (k ascending == global index ascending): first-index tie-break.
        float bd[PPT]; int bk[PPT];
#pragma unroll
        for (int k = 0; k < PPT; k++) { bd[k] = nd[k]; bk[k] = k; }
#pragma unroll
        for (int s = PPT / 2; s > 0; s >>= 1) {
#pragma unroll
            for (int k = 0; k < PPT; k++) {
                if (k < s) {
                    if (bd[k + s] > bd[k]) { bd[k] = bd[k + s]; bk[k] = bk[k + s]; }
                }
            }
        }
        const float best = bd[0];
        const int   bi   = base + bk[0] * T;

        // warp-level: max dist bits, then max of (NN-1-idx) among maxima
        const u32 ub  = __float_as_uint(best);          // dist >= 0: bit order == float order
        const u32 wm  = __reduce_max_sync(0xFFFFFFFFu, ub);
        const u32 cnd = (ub == wm) ? (u32)(NN - 1 - bi) : 0u;
        const u32 wi  = __reduce_max_sync(0xFFFFFFFFu, cnd);

        // all-to-all: leader posts warp key into its slot in every rank
        if (lane == 0) {
            const u64 wkey = ((u64)wm << 32) | ((u64)tag << 16) | (u64)wi;
#pragma unroll
            for (int r = 0; r < CSIZE; r++)
                st_cluster64(peer[r] + bufOff, wkey);
        }

        // every warp: poll all 64 slots (2 per lane), then reduce
        u64 k0, k1;
        do {
            k0 = vld64(poll0 + bufOff);
            k1 = vld64(poll1 + bufOff);
        } while (__any_sync(0xFFFFFFFFu,
                 ((((u32)k0 >> 16) ^ tag) | (((u32)k1 >> 16) ^ tag)) != 0u));

        const u64 k  = (k1 > k0) ? k1 : k0;   // tags equal: dist, then first-index
        const u32 hi = (u32)(k >> 32);
        const u32 lo = (u32)k;
        const u32 M1 = __reduce_max_sync(0xFFFFFFFFu, hi);
        const u32 C1 = (hi == M1) ? lo : 0u;  // tag bits identical across lanes
        const u32 M2 = __reduce_max_sync(0xFFFFFFFFu, C1);
        f = NN - 1 - (int)(M2 & 0x3FFFu);
    }
}

// ---------------------------------------------------------------------------
// Gather feats: out[b][c][m] = feats[b][c][ idx[b][m] ]
// ---------------------------------------------------------------------------
extern "C" __global__ void gather_feats_kernel(const float* __restrict__ feats,
                                               float* __restrict__ out) {
    long long l = (long long)blockIdx.x * blockDim.x + threadIdx.x;
    const long long total = (long long)BB * CC * NPOINT;
    if (l >= total) return;
    int m = (int)(l % NPOINT);
    long long bc = l / NPOINT;          // b*C + c
    int b = (int)(bc / CC);
    int i = g_idx[b * NPOINT + m];
    out[l] = feats[bc * NN + i];
}

// ---------------------------------------------------------------------------
// Gather xyz: out[b][m][d] = xyz[b][idx[b][m]][d]
// ---------------------------------------------------------------------------
extern "C" __global__ void gather_xyz_kernel(const float* __restrict__ xyz,
                                             float* __restrict__ out) {
    int l = blockIdx.x * blockDim.x + threadIdx.x;   // over B*NPOINT
    if (l >= BB * NPOINT) return;
    int b = l / NPOINT;
    int i = g_idx[l];
    const float* src = xyz + ((size_t)b * NN + i) * 3;
    float* dst = out + (size_t)l * 3;
    dst[0] = src[0];
    dst[1] = src[1];
    dst[2] = src[2];
}

// ---------------------------------------------------------------------------
extern "C" void kernel_launch(void* const* d_in, const int* in_sizes, int n_in,
                              void* d_out, int out_size) {
    // Identify inputs by element count (robust to ordering):
    // feats = 8*128*16384 = 16777216, xyz = 8*16384*3 = 393216
    const float* feats = (const float*)d_in[0];
    const float* xyz   = (const float*)d_in[1];
    if (in_sizes[0] == BB * NN * 3) {
        xyz   = (const float*)d_in[0];
        feats = (const float*)d_in[1];
    }

    float* out = (float*)d_out;
    float* out_feats = out;                                   // B*C*NPOINT
    float* out_xyz   = out + (size_t)BB * CC * NPOINT;        // B*NPOINT*3

    const size_t smem = (size_t)3 * NN * sizeof(float)
                      + 2 * NSLOT * sizeof(u64);
    cudaFuncSetAttribute(fps_kernel,
                         cudaFuncAttributeMaxDynamicSharedMemorySize,
                         (int)smem);

    fps_kernel<<<BB * CSIZE, T, smem>>>(xyz);

    const long long feat_total = (long long)BB * CC * NPOINT;
    int gb = (int)((feat_total + 255) / 256);
    gather_feats_kernel<<<gb, 256>>>(feats, out_feats);

    int xb = (BB * NPOINT + 255) / 256;
    gather_xyz_kernel<<<xb, 256>>>(xyz, out_xyz);
}

// round 6
// speedup vs baseline: 3.8671x; 1.1450x over previous
#include <cuda_runtime.h>
#include <cstdint>

// Problem constants (fixed by the reference: B=8, N=16384, RATIO=0.5, C=128)
#define BB 8
#define NN 16384
#define NPOINT 8192
#define CC 128
#define T 256                // threads per CTA (8 warps)
#define CSIZE 8              // CTAs per batch (cluster size)
#define NC (NN / CSIZE)      // 2048 points per CTA
#define NWARP (T / 32)       // 8 warps
#define PPT (NC / T)         // 8 points per thread
#define NSLOT (CSIZE * NWARP)  // 64 cross slots per buffer

typedef unsigned long long u64;
typedef unsigned int u32;

// Scratch: selected indices per batch (device global — no allocation allowed)
__device__ int g_idx[BB * NPOINT];

// ---------------------------------------------------------------------------
// helpers
// ---------------------------------------------------------------------------
__device__ __forceinline__ u32 smem_u32(const void* p) {
    return (u32)__cvta_generic_to_shared(p);
}
__device__ __forceinline__ void vld64x2(u32 a, u64& v0, u64& v1) {
    asm volatile("ld.volatile.shared.v2.u64 {%0, %1}, [%2];"
                 : "=l"(v0), "=l"(v1) : "r"(a) : "memory");
}
__device__ __forceinline__ u32 mapa_rank(u32 laddr, u32 rank) {
    u32 ra;
    asm volatile("mapa.shared::cluster.u32 %0, %1, %2;" : "=r"(ra) : "r"(laddr), "r"(rank));
    return ra;
}
__device__ __forceinline__ void st_cluster64(u32 raddr, u64 v) {
    asm volatile("st.relaxed.cluster.shared::cluster.b64 [%0], %1;" :: "r"(raddr), "l"(v) : "memory");
}

// ---------------------------------------------------------------------------
// FPS: 8-CTA cluster per batch, 256 threads/CTA, 8 points/thread (registers).
// Per-point distance arithmetic is the VERBATIM scalar expression from the
// rel_err==0.0 kernels (rounds 1/3/4/5) — do not touch.
//
// ONE-STAGE all-to-all reduction per iteration:
//   thread:  pairwise argmax tree over 8 points (prefer-left = lower index
//            on ties, exact jnp.argmax semantics)
//   warp:    2x REDUX -> warp key (held by EVERY lane)
//   all-to-all (round-6): lanes 0..7 each issue ONE remote store of the warp
//            key to rank=lane, slot [rank*NWARP+wid] — one SIMT instruction
//            puts all 8 remote stores in flight simultaneously (vs a serial
//            8-store loop on lane 0).
//   every warp: polls all 64 tagged slots, lane L reads the contiguous pair
//            {2L, 2L+1} with a single ld.volatile.v2.u64; local u64 max,
//            then 2x REDUX -> f.
// Keys: (dist_bits<<32) | (tag<<16) | (NN-1-idx); within one iteration all
// tags are equal so u64 max == (max dist, then first index) — jnp.argmax
// tie-breaking. Tags self-synchronize the spin; double buffering (j&1)
// prevents overwrite races: a warp writes buffer (j+2)&1 only after passing
// poll j+1, which required every warp of every rank to have posted j+1,
// which required them to have finished reading buffer j&1.
// ---------------------------------------------------------------------------
extern "C" __global__ void __launch_bounds__(T, 1) __cluster_dims__(CSIZE, 1, 1)
fps_kernel(const float* __restrict__ xyz)
{
    const int blk  = blockIdx.x;
    const int b    = blk / CSIZE;
    const u32 rank = (u32)(blk % CSIZE);
    const int tid  = threadIdx.x;
    const int wid  = tid >> 5;
    const int lane = tid & 31;

    extern __shared__ float smem[];
    float* sx = smem;                               // [NN]
    float* sy = smem + NN;                          // [NN]
    float* sz = smem + 2 * NN;                      // [NN]
    u64* crossSlots = (u64*)(smem + 3 * NN);        // [2][NSLOT], 16B-aligned

    const float* __restrict__ p = xyz + (size_t)b * NN * 3;

    // Full xyz table in smem (centroid lookup must cover all 16384 points)
    for (int i = tid; i < NN; i += T) {
        sx[i] = p[3 * i + 0];
        sy[i] = p[3 * i + 1];
        sz[i] = p[3 * i + 2];
    }
    if (tid < 2 * NSLOT) crossSlots[tid] = 0ull;
    __syncthreads();
    // all CTAs' slots must be zeroed before any peer's first DSMEM store
    asm volatile("barrier.cluster.arrive.aligned;" ::: "memory");
    asm volatile("barrier.cluster.wait.aligned;"   ::: "memory");

    // Own 8 points, register-resident: i_k = base + k*T (k ascending => index ascending)
    const int base = (int)rank * NC + tid;
    float X[PPT], Y[PPT], Z[PPT], D[PPT];
#pragma unroll
    for (int k = 0; k < PPT; k++) {
        const int i = base + k * T;
        X[k] = sx[i]; Y[k] = sy[i]; Z[k] = sz[i];
        D[k] = 1e10f;
    }

    const u32 csBase = smem_u32(crossSlots);

    // Per-lane peer address: lanes 0..7 target rank=lane, slot [rank*NWARP+wid].
    // Single register per thread, computed once.
    const u32 peerAddr = mapa_rank(csBase, (u32)(lane & (CSIZE - 1)))
                       + (u32)(((int)rank * NWARP + wid) * 8);

    // Each lane polls the contiguous slot pair {2*lane, 2*lane+1} (16B, v2).
    const u32 pollAddr = csBase + (u32)(lane * 16);

    int f = 0;   // init_far = 0 (reference)
    int* __restrict__ idxo = g_idx + b * NPOINT;

    for (int j = 0; j < NPOINT; j++) {
        const u32 tag = (u32)(j + 1);   // 1..8192 (14 bits)
        const u32 bufOff = (u32)((j & 1) * (NSLOT * 8));

        if (rank == 0 && tid == 0) idxo[j] = f;  // scan emits farthest BEFORE update

        // distance update — IDENTICAL source expression to rounds 1/3/4/5
        const float cx = sx[f], cy = sy[f], cz = sz[f];
        float nd[PPT];
#pragma unroll
        for (int k = 0; k < PPT; k++) {
            float dx = X[k] - cx;
            float dy = Y[k] - cy;
            float dz = Z[k] - cz;
            float d = dx * dx + dy * dy + dz * dz;
            float v = fminf(D[k], d);
            D[k] = v;
            nd[k] = v;
        }

        // thread-level argmax tree over 8 values; prefer-left keeps lowest k
        // (k ascending == global index ascending): first-index tie-break.
        float bd[PPT]; int bk[PPT];
#pragma unroll
        for (int k = 0; k < PPT; k++) { bd[k] = nd[k]; bk[k] = k; }
#pragma unroll
        for (int s = PPT / 2; s > 0; s >>= 1) {
#pragma unroll
            for (int k = 0; k < PPT; k++) {
                if (k < s) {
                    if (bd[k + s] > bd[k]) { bd[k] = bd[k + s]; bk[k] = bk[k + s]; }
                }
            }
        }
        const float best = bd[0];
        const int   bi   = base + bk[0] * T;

        // warp-level: max dist bits, then max of (NN-1-idx) among maxima
        const u32 ub  = __float_as_uint(best);          // dist >= 0: bit order == float order
        const u32 wm  = __reduce_max_sync(0xFFFFFFFFu, ub);
        const u32 cnd = (ub == wm) ? (u32)(NN - 1 - bi) : 0u;
        const u32 wi  = __reduce_max_sync(0xFFFFFFFFu, cnd);

        // all-to-all: lanes 0..7 each fire ONE remote store (parallel fan-out)
        const u64 wkey = ((u64)wm << 32) | ((u64)tag << 16) | (u64)wi;
        if (lane < CSIZE)
            st_cluster64(peerAddr + bufOff, wkey);

        // every warp: poll all 64 slots (16B pair per lane), then reduce
        u64 k0, k1;
        do {
            vld64x2(pollAddr + bufOff, k0, k1);
        } while (__any_sync(0xFFFFFFFFu,
                 ((((u32)k0 >> 16) ^ tag) | (((u32)k1 >> 16) ^ tag)) != 0u));

        const u64 k  = (k1 > k0) ? k1 : k0;   // tags equal: dist, then first-index
        const u32 hi = (u32)(k >> 32);
        const u32 lo = (u32)k;
        const u32 M1 = __reduce_max_sync(0xFFFFFFFFu, hi);
        const u32 C1 = (hi == M1) ? lo : 0u;  // tag bits identical across lanes
        const u32 M2 = __reduce_max_sync(0xFFFFFFFFu, C1);
        f = NN - 1 - (int)(M2 & 0x3FFFu);
    }
}

// ---------------------------------------------------------------------------
// Gather feats: out[b][c][m] = feats[b][c][ idx[b][m] ]
// ---------------------------------------------------------------------------
extern "C" __global__ void gather_feats_kernel(const float* __restrict__ feats,
                                               float* __restrict__ out) {
    long long l = (long long)blockIdx.x * blockDim.x + threadIdx.x;
    const long long total = (long long)BB * CC * NPOINT;
    if (l >= total) return;
    int m = (int)(l % NPOINT);
    long long bc = l / NPOINT;          // b*C + c
    int b = (int)(bc / CC);
    int i = g_idx[b * NPOINT + m];
    out[l] = feats[bc * NN + i];
}

// ---------------------------------------------------------------------------
// Gather xyz: out[b][m][d] = xyz[b][idx[b][m]][d]
// ---------------------------------------------------------------------------
extern "C" __global__ void gather_xyz_kernel(const float* __restrict__ xyz,
                                             float* __restrict__ out) {
    int l = blockIdx.x * blockDim.x + threadIdx.x;   // over B*NPOINT
    if (l >= BB * NPOINT) return;
    int b = l / NPOINT;
    int i = g_idx[l];
    const float* src = xyz + ((size_t)b * NN + i) * 3;
    float* dst = out + (size_t)l * 3;
    dst[0] = src[0];
    dst[1] = src[1];
    dst[2] = src[2];
}

// ---------------------------------------------------------------------------
extern "C" void kernel_launch(void* const* d_in, const int* in_sizes, int n_in,
                              void* d_out, int out_size) {
    // Identify inputs by element count (robust to ordering):
    // feats = 8*128*16384 = 16777216, xyz = 8*16384*3 = 393216
    const float* feats = (const float*)d_in[0];
    const float* xyz   = (const float*)d_in[1];
    if (in_sizes[0] == BB * NN * 3) {
        xyz   = (const float*)d_in[0];
        feats = (const float*)d_in[1];
    }

    float* out = (float*)d_out;
    float* out_feats = out;                                   // B*C*NPOINT
    float* out_xyz   = out + (size_t)BB * CC * NPOINT;        // B*NPOINT*3

    const size_t smem = (size_t)3 * NN * sizeof(float)
                      + 2 * NSLOT * sizeof(u64);
    cudaFuncSetAttribute(fps_kernel,
                         cudaFuncAttributeMaxDynamicSharedMemorySize,
                         (int)smem);

    fps_kernel<<<BB * CSIZE, T, smem>>>(xyz);

    const long long feat_total = (long long)BB * CC * NPOINT;
    int gb = (int)((feat_total + 255) / 256);
    gather_feats_kernel<<<gb, 256>>>(feats, out_feats);

    int xb = (BB * NPOINT + 255) / 256;
    gather_xyz_kernel<<<xb, 256>>>(xyz, out_xyz);
}